// round 2
// baseline (speedup 1.0000x reference)
#include <cuda_runtime.h>
#include <math.h>

#define BB 128
#define SS 128
#define WW 16
#define CEd 64
#define HHd 256
#define KK 27
#define NSTART 25
#define NSTOP 26
#define NW (BB*SS)

// ---------------- scratch (static device memory; no allocations) ----------------
__device__ float g_hf[NW*CEd];       // char fwd final hidden
__device__ float g_hb[NW*CEd];       // char bwd final hidden
__device__ float g_chvec[NW*CEd];    // char vec [NW,64]
__device__ float g_fv[NW*128];       // feature vec [NW,128]
__device__ float g_vec[NW*320];      // sentence LSTM input [NW,320]
__device__ float g_h[2*BB*HHd];      // running hidden per dir
__device__ float g_c[2*BB*HHd];      // running cell per dir
__device__ float g_hout[NW*512];     // [B,S,512] fwd|bwd hidden
__device__ float g_feats[NW*KK];     // emissions
__device__ int   g_bp[(SS-1)*BB*KK]; // viterbi backpointers

__device__ __forceinline__ float sigmoidf_(float x){ return 1.0f/(1.0f+expf(-x)); }

// ---------------- char BiLSTM: one gate row per thread, weights in registers ----------------
__global__ __launch_bounds__(256,1) void char_lstm_kernel(
    const int* __restrict__ chars2ix, const float* __restrict__ char_emb,
    const float* __restrict__ Wih_f, const float* __restrict__ Whh_f,
    const float* __restrict__ bih_f, const float* __restrict__ bhh_f,
    const float* __restrict__ Wih_b, const float* __restrict__ Whh_b,
    const float* __restrict__ bih_b, const float* __restrict__ bhh_b)
{
    int t = threadIdx.x;            // gate row 0..255
    int dir = blockIdx.y;           // 0 fwd, 1 bwd
    const float* Wih = dir ? Wih_b : Wih_f;
    const float* Whh = dir ? Whh_b : Whh_f;
    const float* bih = dir ? bih_b : bih_f;
    const float* bhh = dir ? bhh_b : bhh_f;
    float* hout = dir ? g_hb : g_hf;

    float wih[CEd], whh[CEd];
    #pragma unroll
    for (int j = 0; j < CEd; j++) { wih[j] = Wih[t*CEd + j]; whh[j] = Whh[t*CEd + j]; }
    float bias = bih[t] + bhh[t];

    __shared__ __align__(16) float xs[WW][CEd];
    __shared__ __align__(16) float hs[CEd];
    __shared__ float cs[CEd];
    __shared__ float gs[256];

    for (int w = blockIdx.x; w < NW; w += gridDim.x) {
        for (int i = t; i < WW*CEd; i += 256) {
            int st = i >> 6, j = i & 63;
            xs[st][j] = char_emb[ chars2ix[w*WW + st]*CEd + j ];
        }
        if (t < CEd) { hs[t] = 0.f; cs[t] = 0.f; }
        __syncthreads();
        #pragma unroll 1
        for (int s = 0; s < WW; s++) {
            int st = dir ? (WW-1-s) : s;
            float a0=0.f, a1=0.f, a2=0.f, a3=0.f;
            #pragma unroll
            for (int j = 0; j < CEd; j += 4) {
                float4 xv = *(const float4*)&xs[st][j];
                float4 hv = *(const float4*)&hs[j];
                a0 += wih[j+0]*xv.x; a1 += wih[j+1]*xv.y;
                a2 += wih[j+2]*xv.z; a3 += wih[j+3]*xv.w;
                a0 += whh[j+0]*hv.x; a1 += whh[j+1]*hv.y;
                a2 += whh[j+2]*hv.z; a3 += whh[j+3]*hv.w;
            }
            gs[t] = a0 + a1 + a2 + a3 + bias;
            __syncthreads();
            if (t < CEd) {
                float iv = sigmoidf_(gs[t]);
                float fv = sigmoidf_(gs[t+64]);
                float gv = tanhf(gs[t+128]);
                float ov = sigmoidf_(gs[t+192]);
                float c = fv*cs[t] + iv*gv;
                cs[t] = c;
                hs[t] = ov*tanhf(c);
            }
            __syncthreads();
        }
        if (t < CEd) hout[w*CEd + t] = hs[t];
        __syncthreads();
    }
}

// ---------------- chvec = [hf|hb] @ char_out_W^T + b ----------------
__global__ void chvec_kernel(const float* __restrict__ coW, const float* __restrict__ cob)
{
    for (int i = blockIdx.x*blockDim.x + threadIdx.x; i < NW*CEd; i += gridDim.x*blockDim.x) {
        int w = i >> 6, m = i & 63;
        float acc = cob[m];
        const float* wr = coW + m*128;
        const float* hf = g_hf + w*CEd;
        const float* hb = g_hb + w*CEd;
        #pragma unroll 8
        for (int j = 0; j < 64; j++) acc += wr[j]*hf[j];
        #pragma unroll 8
        for (int j = 0; j < 64; j++) acc += wr[64+j]*hb[j];
        g_chvec[i] = acc;
    }
}

// ---------------- fv + assemble vec = [word_emb | chvec | fv] ----------------
__global__ void fv_vec_kernel(const float* __restrict__ features,
                              const float* __restrict__ featW, const float* __restrict__ featb,
                              const int* __restrict__ words2ix, const float* __restrict__ word_emb)
{
    for (int idx = blockIdx.x*blockDim.x + threadIdx.x; idx < NW*320; idx += gridDim.x*blockDim.x) {
        int w = idx / 320;
        int j = idx - w*320;
        float v;
        if (j < 128) {
            v = word_emb[ words2ix[w]*128 + j ];
        } else if (j < 192) {
            v = g_chvec[w*64 + (j-128)];
        } else {
            int m = j - 192;
            int b = w >> 7, s = w & 127;
            v = featb[m];
            #pragma unroll
            for (int f = 0; f < 4; f++) v += featW[m*4+f]*features[(b*4+f)*SS + s];
            g_fv[w*128 + m] = v;
        }
        g_vec[idx] = v;
    }
}

// ---------------- sentence BiLSTM: one launch per time step ----------------
// block = (dir, 32-unit slice, 16-seq group); thread = (unit, 2 seqs), all 4 gates
__global__ __launch_bounds__(256,1) void lstm_step_kernel(
    const float* __restrict__ Wih_f, const float* __restrict__ Whh_f,
    const float* __restrict__ bih_f, const float* __restrict__ bhh_f,
    const float* __restrict__ Wih_b, const float* __restrict__ Whh_b,
    const float* __restrict__ bih_b, const float* __restrict__ bhh_b,
    int t)
{
    int bx = blockIdx.x;
    int dir = bx >> 6;
    int us  = (bx >> 3) & 7;
    int sg  = bx & 7;
    const float* Wih = dir ? Wih_b : Wih_f;
    const float* Whh = dir ? Whh_b : Whh_f;
    const float* bih = dir ? bih_b : bih_f;
    const float* bhh = dir ? bhh_b : bhh_f;
    int tx = dir ? (SS-1-t) : t;
    int sbase = sg*16;

    __shared__ __align__(16) float xh[576][16];   // transposed: [feature][seq]

    int tid = threadIdx.x;
    for (int i = tid; i < 16*576; i += 256) {
        int s = i / 576; int j = i - s*576;
        int sb = sbase + s;
        float v;
        if (j < 320) v = g_vec[(sb*SS + tx)*320 + j];
        else {
            int u = j - 320;
            v = (t == 0) ? 0.f : g_h[dir*BB*HHd + sb*HHd + u];
        }
        xh[j][s] = v;
    }
    __syncthreads();

    int lu = tid >> 3;            // 0..31
    int u  = us*32 + lu;          // unit 0..255
    int s0 = 2*(tid & 7);         // local seq pair base (even)
    int r0 = u, r1 = 256+u, r2 = 512+u, r3 = 768+u;

    float acc[4][2];
    #pragma unroll
    for (int g = 0; g < 4; g++) { acc[g][0] = 0.f; acc[g][1] = 0.f; }

    #pragma unroll 4
    for (int j = 0; j < 320; j += 4) {
        float4 w0 = *(const float4*)(Wih + r0*320 + j);
        float4 w1 = *(const float4*)(Wih + r1*320 + j);
        float4 w2 = *(const float4*)(Wih + r2*320 + j);
        float4 w3 = *(const float4*)(Wih + r3*320 + j);
        #pragma unroll
        for (int q = 0; q < 4; q++) {
            float2 xv = *(const float2*)&xh[j+q][s0];
            float a = ((const float*)&w0)[q];
            float b = ((const float*)&w1)[q];
            float c = ((const float*)&w2)[q];
            float d = ((const float*)&w3)[q];
            acc[0][0] += a*xv.x; acc[0][1] += a*xv.y;
            acc[1][0] += b*xv.x; acc[1][1] += b*xv.y;
            acc[2][0] += c*xv.x; acc[2][1] += c*xv.y;
            acc[3][0] += d*xv.x; acc[3][1] += d*xv.y;
        }
    }
    #pragma unroll 4
    for (int j = 0; j < 256; j += 4) {
        float4 w0 = *(const float4*)(Whh + r0*256 + j);
        float4 w1 = *(const float4*)(Whh + r1*256 + j);
        float4 w2 = *(const float4*)(Whh + r2*256 + j);
        float4 w3 = *(const float4*)(Whh + r3*256 + j);
        #pragma unroll
        for (int q = 0; q < 4; q++) {
            float2 xv = *(const float2*)&xh[320+j+q][s0];
            float a = ((const float*)&w0)[q];
            float b = ((const float*)&w1)[q];
            float c = ((const float*)&w2)[q];
            float d = ((const float*)&w3)[q];
            acc[0][0] += a*xv.x; acc[0][1] += a*xv.y;
            acc[1][0] += b*xv.x; acc[1][1] += b*xv.y;
            acc[2][0] += c*xv.x; acc[2][1] += c*xv.y;
            acc[3][0] += d*xv.x; acc[3][1] += d*xv.y;
        }
    }

    float bi0 = bih[r0] + bhh[r0];
    float bi1 = bih[r1] + bhh[r1];
    float bi2 = bih[r2] + bhh[r2];
    float bi3 = bih[r3] + bhh[r3];

    #pragma unroll
    for (int q = 0; q < 2; q++) {
        int sb = sbase + s0 + q;
        float iv = sigmoidf_(acc[0][q] + bi0);
        float fv = sigmoidf_(acc[1][q] + bi1);
        float gv = tanhf   (acc[2][q] + bi2);
        float ov = sigmoidf_(acc[3][q] + bi3);
        float cp = (t == 0) ? 0.f : g_c[dir*BB*HHd + sb*HHd + u];
        float c  = fv*cp + iv*gv;
        g_c[dir*BB*HHd + sb*HHd + u] = c;
        float h  = ov*tanhf(c);
        g_h[dir*BB*HHd + sb*HHd + u] = h;
        g_hout[(sb*SS + tx)*512 + dir*256 + u] = h;
    }
}

// ---------------- emissions + tag argmax (one warp per token) ----------------
__global__ void feats_kernel(const float* __restrict__ tagW, const float* __restrict__ tagb,
                             float* __restrict__ out)
{
    int w = blockIdx.x;
    int lane = threadIdx.x;
    float xv[22];
    #pragma unroll
    for (int i = 0; i < 22; i++) {
        int j = lane + 32*i;
        float v;
        if (j < 512)      v = g_hout[w*512 + j];
        else if (j < 576) v = g_chvec[w*64 + (j-512)];
        else              v = g_fv[w*128 + (j-576)];
        xv[i] = v;
    }
    float best = -1e30f; int bestk = 0;
    for (int k = 0; k < KK; k++) {
        float acc = 0.f;
        const float* wr = tagW + k*704;
        #pragma unroll
        for (int i = 0; i < 22; i++) acc += wr[lane + 32*i]*xv[i];
        #pragma unroll
        for (int off = 16; off; off >>= 1) acc += __shfl_xor_sync(0xffffffffu, acc, off);
        acc += tagb[k];
        if (lane == 0) g_feats[w*KK + k] = acc;
        if (acc > best) { best = acc; bestk = k; }
    }
    if (lane == 0) out[BB + NW + w] = (float)bestk;
}

// ---------------- CRF Viterbi (one warp per batch element) ----------------
__global__ void viterbi_kernel(const int* __restrict__ mask, const float* __restrict__ trans,
                               float* __restrict__ out)
{
    int b = blockIdx.x;
    int k = threadIdx.x;                  // 32 threads, k<27 active
    __shared__ float sc[KK];
    __shared__ float tr[KK*KK];
    __shared__ float fins[32];
    for (int i = k; i < KK*KK; i += 32) tr[i] = trans[i];
    if (k < KK) sc[k] = g_feats[(b*SS + 0)*KK + k] + trans[NSTART*KK + k];
    __syncwarp();
    for (int step = 1; step < SS; step++) {
        float best = -1e30f; int bp = 0;
        if (k < KK) {
            #pragma unroll
            for (int p = 0; p < KK; p++) {
                float v = sc[p] + tr[p*KK + k];
                if (v > best) { best = v; bp = p; }
            }
            best += g_feats[(b*SS + step)*KK + k];
            if (mask[b*SS + step] == 0) { best = sc[k]; bp = k; }
        }
        __syncwarp();
        if (k < KK) { sc[k] = best; g_bp[((step-1)*BB + b)*KK + k] = bp; }
        __syncwarp();
    }
    float fin = (k < KK) ? (sc[k] + tr[k*KK + NSTOP]) : -1e30f;
    fins[k] = fin;
    __syncwarp();
    if (k == 0) {
        float best = -1e30f; int bt = 0;
        for (int p = 0; p < KK; p++) if (fins[p] > best) { best = fins[p]; bt = p; }
        out[b] = best;
        int tag = bt;
        out[BB + b*SS + (SS-1)] = (float)tag;
        for (int step = SS-1; step >= 1; step--) {
            tag = g_bp[((step-1)*BB + b)*KK + tag];
            out[BB + b*SS + (step-1)] = (float)tag;
        }
    }
}

// ---------------- launch ----------------
extern "C" void kernel_launch(void* const* d_in, const int* in_sizes, int n_in,
                              void* d_out, int out_size)
{
    (void)in_sizes; (void)n_in; (void)out_size;
    const int*   words2ix  = (const int*)  d_in[0];
    const int*   chars2ix  = (const int*)  d_in[1];
    const float* features  = (const float*)d_in[2];
    const int*   mask      = (const int*)  d_in[3];
    const float* word_emb  = (const float*)d_in[4];
    const float* char_emb  = (const float*)d_in[5];
    const float* cWih_f = (const float*)d_in[6];
    const float* cWhh_f = (const float*)d_in[7];
    const float* cbih_f = (const float*)d_in[8];
    const float* cbhh_f = (const float*)d_in[9];
    const float* cWih_b = (const float*)d_in[10];
    const float* cWhh_b = (const float*)d_in[11];
    const float* cbih_b = (const float*)d_in[12];
    const float* cbhh_b = (const float*)d_in[13];
    const float* coW    = (const float*)d_in[14];
    const float* cob    = (const float*)d_in[15];
    const float* featW  = (const float*)d_in[16];
    const float* featb  = (const float*)d_in[17];
    const float* lWih_f = (const float*)d_in[18];
    const float* lWhh_f = (const float*)d_in[19];
    const float* lbih_f = (const float*)d_in[20];
    const float* lbhh_f = (const float*)d_in[21];
    const float* lWih_b = (const float*)d_in[22];
    const float* lWhh_b = (const float*)d_in[23];
    const float* lbih_b = (const float*)d_in[24];
    const float* lbhh_b = (const float*)d_in[25];
    const float* tagW   = (const float*)d_in[26];
    const float* tagb   = (const float*)d_in[27];
    const float* trans  = (const float*)d_in[28];
    float* out = (float*)d_out;

    char_lstm_kernel<<<dim3(512,2), 256>>>(chars2ix, char_emb,
        cWih_f, cWhh_f, cbih_f, cbhh_f, cWih_b, cWhh_b, cbih_b, cbhh_b);
    chvec_kernel<<<512, 256>>>(coW, cob);
    fv_vec_kernel<<<512, 256>>>(features, featW, featb, words2ix, word_emb);
    for (int t = 0; t < SS; t++) {
        lstm_step_kernel<<<128, 256>>>(lWih_f, lWhh_f, lbih_f, lbhh_f,
                                       lWih_b, lWhh_b, lbih_b, lbhh_b, t);
    }
    feats_kernel<<<NW, 32>>>(tagW, tagb, out);
    viterbi_kernel<<<BB, 32>>>(mask, trans, out);
}

// round 3
// speedup vs baseline: 1.0011x; 1.0011x over previous
#include <cuda_runtime.h>
#include <math.h>

#define BB 128
#define SS 128
#define WW 16
#define CEd 64
#define HHd 256
#define KK 27
#define NSTART 25
#define NSTOP 26
#define NW (BB*SS)

// ---------------- scratch (static device memory; no allocations) ----------------
__device__ float g_hf[NW*CEd];       // char fwd final hidden
__device__ float g_hb[NW*CEd];       // char bwd final hidden
__device__ float g_chvec[NW*CEd];    // char vec [NW,64]
__device__ float g_fv[NW*128];       // feature vec [NW,128]
__device__ float g_vec[NW*320];      // sentence LSTM input [NW,320]
__device__ float g_h[2*BB*HHd];      // running hidden per dir
__device__ float g_c[2*BB*HHd];      // running cell per dir
__device__ float g_hout[NW*512];     // [B,S,512] fwd|bwd hidden
__device__ float g_feats[NW*KK];     // emissions
__device__ int   g_bp[(SS-1)*BB*KK]; // viterbi backpointers

__device__ __forceinline__ float sigmoidf_(float x){ return 1.0f/(1.0f+expf(-x)); }

// ---------------- char BiLSTM: one gate row per thread, weights in registers ----------------
__global__ __launch_bounds__(256,1) void char_lstm_kernel(
    const int* __restrict__ chars2ix, const float* __restrict__ char_emb,
    const float* __restrict__ Wih_f, const float* __restrict__ Whh_f,
    const float* __restrict__ bih_f, const float* __restrict__ bhh_f,
    const float* __restrict__ Wih_b, const float* __restrict__ Whh_b,
    const float* __restrict__ bih_b, const float* __restrict__ bhh_b)
{
    int t = threadIdx.x;            // gate row 0..255
    int dir = blockIdx.y;           // 0 fwd, 1 bwd
    const float* Wih = dir ? Wih_b : Wih_f;
    const float* Whh = dir ? Whh_b : Whh_f;
    const float* bih = dir ? bih_b : bih_f;
    const float* bhh = dir ? bhh_b : bhh_f;
    float* hout = dir ? g_hb : g_hf;

    float wih[CEd], whh[CEd];
    #pragma unroll
    for (int j = 0; j < CEd; j++) { wih[j] = Wih[t*CEd + j]; whh[j] = Whh[t*CEd + j]; }
    float bias = bih[t] + bhh[t];

    __shared__ __align__(16) float xs[WW][CEd];
    __shared__ __align__(16) float hs[CEd];
    __shared__ float cs[CEd];
    __shared__ float gs[256];

    for (int w = blockIdx.x; w < NW; w += gridDim.x) {
        for (int i = t; i < WW*CEd; i += 256) {
            int st = i >> 6, j = i & 63;
            xs[st][j] = char_emb[ chars2ix[w*WW + st]*CEd + j ];
        }
        if (t < CEd) { hs[t] = 0.f; cs[t] = 0.f; }
        __syncthreads();
        #pragma unroll 1
        for (int s = 0; s < WW; s++) {
            int st = dir ? (WW-1-s) : s;
            float a0=0.f, a1=0.f, a2=0.f, a3=0.f;
            #pragma unroll
            for (int j = 0; j < CEd; j += 4) {
                float4 xv = *(const float4*)&xs[st][j];
                float4 hv = *(const float4*)&hs[j];
                a0 += wih[j+0]*xv.x; a1 += wih[j+1]*xv.y;
                a2 += wih[j+2]*xv.z; a3 += wih[j+3]*xv.w;
                a0 += whh[j+0]*hv.x; a1 += whh[j+1]*hv.y;
                a2 += whh[j+2]*hv.z; a3 += whh[j+3]*hv.w;
            }
            gs[t] = a0 + a1 + a2 + a3 + bias;
            __syncthreads();
            if (t < CEd) {
                float iv = sigmoidf_(gs[t]);
                float fv = sigmoidf_(gs[t+64]);
                float gv = tanhf(gs[t+128]);
                float ov = sigmoidf_(gs[t+192]);
                float c = fv*cs[t] + iv*gv;
                cs[t] = c;
                hs[t] = ov*tanhf(c);
            }
            __syncthreads();
        }
        if (t < CEd) hout[w*CEd + t] = hs[t];
        __syncthreads();
    }
}

// ---------------- chvec = [hf|hb] @ char_out_W^T + b ----------------
__global__ void chvec_kernel(const float* __restrict__ coW, const float* __restrict__ cob)
{
    for (int i = blockIdx.x*blockDim.x + threadIdx.x; i < NW*CEd; i += gridDim.x*blockDim.x) {
        int w = i >> 6, m = i & 63;
        float acc = cob[m];
        const float* wr = coW + m*128;
        const float* hf = g_hf + w*CEd;
        const float* hb = g_hb + w*CEd;
        #pragma unroll 8
        for (int j = 0; j < 64; j++) acc += wr[j]*hf[j];
        #pragma unroll 8
        for (int j = 0; j < 64; j++) acc += wr[64+j]*hb[j];
        g_chvec[i] = acc;
    }
}

// ---------------- fv + assemble vec = [word_emb | chvec | fv] ----------------
__global__ void fv_vec_kernel(const float* __restrict__ features,
                              const float* __restrict__ featW, const float* __restrict__ featb,
                              const int* __restrict__ words2ix, const float* __restrict__ word_emb)
{
    for (int idx = blockIdx.x*blockDim.x + threadIdx.x; idx < NW*320; idx += gridDim.x*blockDim.x) {
        int w = idx / 320;
        int j = idx - w*320;
        float v;
        if (j < 128) {
            v = word_emb[ words2ix[w]*128 + j ];
        } else if (j < 192) {
            v = g_chvec[w*64 + (j-128)];
        } else {
            int m = j - 192;
            int b = w >> 7, s = w & 127;
            v = featb[m];
            #pragma unroll
            for (int f = 0; f < 4; f++) v += featW[m*4+f]*features[(b*4+f)*SS + s];
            g_fv[w*128 + m] = v;
        }
        g_vec[idx] = v;
    }
}

// ---------------- sentence BiLSTM: one launch per time step ----------------
// block = (dir, 32-unit slice, 16-seq group); thread = (unit, 2 seqs), all 4 gates
__global__ __launch_bounds__(256,1) void lstm_step_kernel(
    const float* __restrict__ Wih_f, const float* __restrict__ Whh_f,
    const float* __restrict__ bih_f, const float* __restrict__ bhh_f,
    const float* __restrict__ Wih_b, const float* __restrict__ Whh_b,
    const float* __restrict__ bih_b, const float* __restrict__ bhh_b,
    int t)
{
    int bx = blockIdx.x;
    int dir = bx >> 6;
    int us  = (bx >> 3) & 7;
    int sg  = bx & 7;
    const float* Wih = dir ? Wih_b : Wih_f;
    const float* Whh = dir ? Whh_b : Whh_f;
    const float* bih = dir ? bih_b : bih_f;
    const float* bhh = dir ? bhh_b : bhh_f;
    int tx = dir ? (SS-1-t) : t;
    int sbase = sg*16;

    __shared__ __align__(16) float xh[576][16];   // transposed: [feature][seq]

    int tid = threadIdx.x;
    for (int i = tid; i < 16*576; i += 256) {
        int s = i / 576; int j = i - s*576;
        int sb = sbase + s;
        float v;
        if (j < 320) v = g_vec[(sb*SS + tx)*320 + j];
        else {
            int u = j - 320;
            v = (t == 0) ? 0.f : g_h[dir*BB*HHd + sb*HHd + u];
        }
        xh[j][s] = v;
    }
    __syncthreads();

    int lu = tid >> 3;            // 0..31
    int u  = us*32 + lu;          // unit 0..255
    int s0 = 2*(tid & 7);         // local seq pair base (even)
    int r0 = u, r1 = 256+u, r2 = 512+u, r3 = 768+u;

    float acc[4][2];
    #pragma unroll
    for (int g = 0; g < 4; g++) { acc[g][0] = 0.f; acc[g][1] = 0.f; }

    #pragma unroll 4
    for (int j = 0; j < 320; j += 4) {
        float4 w0 = *(const float4*)(Wih + r0*320 + j);
        float4 w1 = *(const float4*)(Wih + r1*320 + j);
        float4 w2 = *(const float4*)(Wih + r2*320 + j);
        float4 w3 = *(const float4*)(Wih + r3*320 + j);
        #pragma unroll
        for (int q = 0; q < 4; q++) {
            float2 xv = *(const float2*)&xh[j+q][s0];
            float a = ((const float*)&w0)[q];
            float b = ((const float*)&w1)[q];
            float c = ((const float*)&w2)[q];
            float d = ((const float*)&w3)[q];
            acc[0][0] += a*xv.x; acc[0][1] += a*xv.y;
            acc[1][0] += b*xv.x; acc[1][1] += b*xv.y;
            acc[2][0] += c*xv.x; acc[2][1] += c*xv.y;
            acc[3][0] += d*xv.x; acc[3][1] += d*xv.y;
        }
    }
    #pragma unroll 4
    for (int j = 0; j < 256; j += 4) {
        float4 w0 = *(const float4*)(Whh + r0*256 + j);
        float4 w1 = *(const float4*)(Whh + r1*256 + j);
        float4 w2 = *(const float4*)(Whh + r2*256 + j);
        float4 w3 = *(const float4*)(Whh + r3*256 + j);
        #pragma unroll
        for (int q = 0; q < 4; q++) {
            float2 xv = *(const float2*)&xh[320+j+q][s0];
            float a = ((const float*)&w0)[q];
            float b = ((const float*)&w1)[q];
            float c = ((const float*)&w2)[q];
            float d = ((const float*)&w3)[q];
            acc[0][0] += a*xv.x; acc[0][1] += a*xv.y;
            acc[1][0] += b*xv.x; acc[1][1] += b*xv.y;
            acc[2][0] += c*xv.x; acc[2][1] += c*xv.y;
            acc[3][0] += d*xv.x; acc[3][1] += d*xv.y;
        }
    }

    float bi0 = bih[r0] + bhh[r0];
    float bi1 = bih[r1] + bhh[r1];
    float bi2 = bih[r2] + bhh[r2];
    float bi3 = bih[r3] + bhh[r3];

    #pragma unroll
    for (int q = 0; q < 2; q++) {
        int sb = sbase + s0 + q;
        float iv = sigmoidf_(acc[0][q] + bi0);
        float fv = sigmoidf_(acc[1][q] + bi1);
        float gv = tanhf   (acc[2][q] + bi2);
        float ov = sigmoidf_(acc[3][q] + bi3);
        float cp = (t == 0) ? 0.f : g_c[dir*BB*HHd + sb*HHd + u];
        float c  = fv*cp + iv*gv;
        g_c[dir*BB*HHd + sb*HHd + u] = c;
        float h  = ov*tanhf(c);
        g_h[dir*BB*HHd + sb*HHd + u] = h;
        g_hout[(sb*SS + tx)*512 + dir*256 + u] = h;
    }
}

// ---------------- emissions + tag argmax (one warp per token) ----------------
__global__ void feats_kernel(const float* __restrict__ tagW, const float* __restrict__ tagb,
                             float* __restrict__ out)
{
    int w = blockIdx.x;
    int lane = threadIdx.x;
    float xv[22];
    #pragma unroll
    for (int i = 0; i < 22; i++) {
        int j = lane + 32*i;
        float v;
        if (j < 512)      v = g_hout[w*512 + j];
        else if (j < 576) v = g_chvec[w*64 + (j-512)];
        else              v = g_fv[w*128 + (j-576)];
        xv[i] = v;
    }
    float best = -1e30f; int bestk = 0;
    for (int k = 0; k < KK; k++) {
        float acc = 0.f;
        const float* wr = tagW + k*704;
        #pragma unroll
        for (int i = 0; i < 22; i++) acc += wr[lane + 32*i]*xv[i];
        #pragma unroll
        for (int off = 16; off; off >>= 1) acc += __shfl_xor_sync(0xffffffffu, acc, off);
        acc += tagb[k];
        if (lane == 0) g_feats[w*KK + k] = acc;
        if (acc > best) { best = acc; bestk = k; }
    }
    if (lane == 0) out[BB + NW + w] = (float)bestk;
}

// ---------------- CRF Viterbi (one warp per batch element) ----------------
__global__ void viterbi_kernel(const int* __restrict__ mask, const float* __restrict__ trans,
                               float* __restrict__ out)
{
    int b = blockIdx.x;
    int k = threadIdx.x;                  // 32 threads, k<27 active
    __shared__ float sc[KK];
    __shared__ float tr[KK*KK];
    __shared__ float fins[32];
    for (int i = k; i < KK*KK; i += 32) tr[i] = trans[i];
    if (k < KK) sc[k] = g_feats[(b*SS + 0)*KK + k] + trans[NSTART*KK + k];
    __syncwarp();
    for (int step = 1; step < SS; step++) {
        float best = -1e30f; int bp = 0;
        if (k < KK) {
            #pragma unroll
            for (int p = 0; p < KK; p++) {
                float v = sc[p] + tr[p*KK + k];
                if (v > best) { best = v; bp = p; }
            }
            best += g_feats[(b*SS + step)*KK + k];
            if (mask[b*SS + step] == 0) { best = sc[k]; bp = k; }
        }
        __syncwarp();
        if (k < KK) { sc[k] = best; g_bp[((step-1)*BB + b)*KK + k] = bp; }
        __syncwarp();
    }
    float fin = (k < KK) ? (sc[k] + tr[k*KK + NSTOP]) : -1e30f;
    fins[k] = fin;
    __syncwarp();
    if (k == 0) {
        float best = -1e30f; int bt = 0;
        for (int p = 0; p < KK; p++) if (fins[p] > best) { best = fins[p]; bt = p; }
        out[b] = best;
        int tag = bt;
        out[BB + b*SS + (SS-1)] = (float)tag;
        for (int step = SS-1; step >= 1; step--) {
            tag = g_bp[((step-1)*BB + b)*KK + tag];
            out[BB + b*SS + (step-1)] = (float)tag;
        }
    }
}

// ---------------- launch ----------------
extern "C" void kernel_launch(void* const* d_in, const int* in_sizes, int n_in,
                              void* d_out, int out_size)
{
    (void)in_sizes; (void)n_in; (void)out_size;
    const int*   words2ix  = (const int*)  d_in[0];
    const int*   chars2ix  = (const int*)  d_in[1];
    const float* features  = (const float*)d_in[2];
    const int*   mask      = (const int*)  d_in[3];
    const float* word_emb  = (const float*)d_in[4];
    const float* char_emb  = (const float*)d_in[5];
    const float* cWih_f = (const float*)d_in[6];
    const float* cWhh_f = (const float*)d_in[7];
    const float* cbih_f = (const float*)d_in[8];
    const float* cbhh_f = (const float*)d_in[9];
    const float* cWih_b = (const float*)d_in[10];
    const float* cWhh_b = (const float*)d_in[11];
    const float* cbih_b = (const float*)d_in[12];
    const float* cbhh_b = (const float*)d_in[13];
    const float* coW    = (const float*)d_in[14];
    const float* cob    = (const float*)d_in[15];
    const float* featW  = (const float*)d_in[16];
    const float* featb  = (const float*)d_in[17];
    const float* lWih_f = (const float*)d_in[18];
    const float* lWhh_f = (const float*)d_in[19];
    const float* lbih_f = (const float*)d_in[20];
    const float* lbhh_f = (const float*)d_in[21];
    const float* lWih_b = (const float*)d_in[22];
    const float* lWhh_b = (const float*)d_in[23];
    const float* lbih_b = (const float*)d_in[24];
    const float* lbhh_b = (const float*)d_in[25];
    const float* tagW   = (const float*)d_in[26];
    const float* tagb   = (const float*)d_in[27];
    const float* trans  = (const float*)d_in[28];
    float* out = (float*)d_out;

    char_lstm_kernel<<<dim3(512,2), 256>>>(chars2ix, char_emb,
        cWih_f, cWhh_f, cbih_f, cbhh_f, cWih_b, cWhh_b, cbih_b, cbhh_b);
    chvec_kernel<<<512, 256>>>(coW, cob);
    fv_vec_kernel<<<512, 256>>>(features, featW, featb, words2ix, word_emb);
    for (int t = 0; t < SS; t++) {
        lstm_step_kernel<<<128, 256>>>(lWih_f, lWhh_f, lbih_f, lbhh_f,
                                       lWih_b, lWhh_b, lbih_b, lbhh_b, t);
    }
    feats_kernel<<<NW, 32>>>(tagW, tagb, out);
    viterbi_kernel<<<BB, 32>>>(mask, trans, out);
}

// round 4
// speedup vs baseline: 1.4393x; 1.4377x over previous
#include <cuda_runtime.h>
#include <math.h>

#define BB 128
#define SS 128
#define WW 16
#define CEd 64
#define HHd 256
#define KK 27
#define NSTART 25
#define NSTOP 26
#define NW (BB*SS)

typedef unsigned long long u64;

__device__ __forceinline__ u64 pack2(float a, float b){ u64 r; asm("mov.b64 %0,{%1,%2};":"=l"(r):"f"(a),"f"(b)); return r; }
__device__ __forceinline__ float2 unpack2(u64 v){ float2 f; asm("mov.b64 {%0,%1},%2;":"=f"(f.x),"=f"(f.y):"l"(v)); return f; }
__device__ __forceinline__ u64 ffma2(u64 a, u64 b, u64 c){ u64 d; asm("fma.rn.f32x2 %0,%1,%2,%3;":"=l"(d):"l"(a),"l"(b),"l"(c)); return d; }
__device__ __forceinline__ u64 add2(u64 a, u64 b){ u64 d; asm("add.rn.f32x2 %0,%1,%2;":"=l"(d):"l"(a),"l"(b)); return d; }

__device__ __forceinline__ float sigf(float x){ return 1.0f/(1.0f+__expf(-x)); }
__device__ __forceinline__ float tanhfast(float x){ return 2.0f/(1.0f+__expf(-2.0f*x)) - 1.0f; }

// ---------------- static scratch ----------------
__device__ float g_hf[NW*CEd];
__device__ float g_hb[NW*CEd];
__device__ float g_chvec[NW*CEd];
__device__ float g_fv[NW*128];
__device__ float g_vec[NW*320];
__device__ float g_gx[2*SS*BB*1024];      // [dir][t][b][1024]
__device__ float g_hT[2*2*8*4096];        // [buf][dir][sg][256u][16s]
__device__ float g_hout[NW*512];
__device__ float g_feats[NW*KK];
__device__ int   g_bp[(SS-1)*BB*KK];
__device__ unsigned g_bar_arrive;
__device__ volatile unsigned g_bar_release;

// ---------------- char BiLSTM: 4 words per block-iter, f32x2 over word pairs ----------------
__global__ __launch_bounds__(256,1) void char_lstm_kernel(
    const int* __restrict__ chars2ix, const float* __restrict__ char_emb,
    const float* __restrict__ Wih_f, const float* __restrict__ Whh_f,
    const float* __restrict__ bih_f, const float* __restrict__ bhh_f,
    const float* __restrict__ Wih_b, const float* __restrict__ Whh_b,
    const float* __restrict__ bih_b, const float* __restrict__ bhh_b)
{
    int t = threadIdx.x;            // gate row 0..255
    int dir = blockIdx.y;
    const float* Wih = dir ? Wih_b : Wih_f;
    const float* Whh = dir ? Whh_b : Whh_f;
    const float* bih = dir ? bih_b : bih_f;
    const float* bhh = dir ? bhh_b : bhh_f;
    float* hout = dir ? g_hb : g_hf;

    float wih[CEd], whh[CEd];
    #pragma unroll
    for (int j = 0; j < CEd; j++) { wih[j] = Wih[t*CEd + j]; whh[j] = Whh[t*CEd + j]; }
    float bias = bih[t] + bhh[t];

    __shared__ __align__(16) float xs[WW][CEd][4];
    __shared__ __align__(16) float hs[CEd][4];
    __shared__ float cs[4][CEd];
    __shared__ __align__(16) float gs[256][4];
    __shared__ int cix[64];

    for (int q = blockIdx.x; q < NW/4; q += gridDim.x) {
        int w0 = q*4;
        if (t < 64) cix[t] = chars2ix[(w0 + (t>>4))*WW + (t&15)];
        __syncthreads();
        for (int i = t; i < 1024; i += 256) {
            int st = i>>6, j = i&63;
            float4 v;
            v.x = char_emb[cix[0*16+st]*CEd + j];
            v.y = char_emb[cix[1*16+st]*CEd + j];
            v.z = char_emb[cix[2*16+st]*CEd + j];
            v.w = char_emb[cix[3*16+st]*CEd + j];
            *(float4*)&xs[st][j][0] = v;
        }
        if (t < 64) {
            *(float4*)&hs[t][0] = make_float4(0.f,0.f,0.f,0.f);
            cs[0][t]=0.f; cs[1][t]=0.f; cs[2][t]=0.f; cs[3][t]=0.f;
        }
        __syncthreads();

        #pragma unroll 1
        for (int s = 0; s < WW; s++) {
            int st = dir ? (WW-1-s) : s;
            u64 a01 = 0ull, a23 = 0ull;
            #pragma unroll
            for (int j = 0; j < CEd; j++) {
                ulonglong2 xv = *(const ulonglong2*)&xs[st][j][0];
                ulonglong2 hv = *(const ulonglong2*)&hs[j][0];
                u64 wi = pack2(wih[j], wih[j]);
                u64 wh = pack2(whh[j], whh[j]);
                a01 = ffma2(wi, xv.x, a01); a23 = ffma2(wi, xv.y, a23);
                a01 = ffma2(wh, hv.x, a01); a23 = ffma2(wh, hv.y, a23);
            }
            float2 f01 = unpack2(a01), f23 = unpack2(a23);
            *(float4*)&gs[t][0] = make_float4(f01.x+bias, f01.y+bias, f23.x+bias, f23.y+bias);
            __syncthreads();
            {
                int w = t>>6, u = t&63;
                float iv = sigf(gs[u][w]);
                float fv = sigf(gs[64+u][w]);
                float gg = tanhfast(gs[128+u][w]);
                float ov = sigf(gs[192+u][w]);
                float c = fv*cs[w][u] + iv*gg;
                cs[w][u] = c;
                hs[u][w] = ov*tanhfast(c);
            }
            __syncthreads();
        }
        { int w = t>>6, u = t&63; hout[(w0+w)*CEd + u] = hs[u][w]; }
        __syncthreads();
    }
}

// ---------------- chvec = [hf|hb] @ char_out_W^T + b ----------------
__global__ void chvec_kernel(const float* __restrict__ coW, const float* __restrict__ cob)
{
    for (int i = blockIdx.x*blockDim.x + threadIdx.x; i < NW*CEd; i += gridDim.x*blockDim.x) {
        int w = i >> 6, m = i & 63;
        float acc = cob[m];
        const float* wr = coW + m*128;
        const float* hf = g_hf + w*CEd;
        const float* hb = g_hb + w*CEd;
        #pragma unroll 8
        for (int j = 0; j < 64; j++) acc += wr[j]*hf[j];
        #pragma unroll 8
        for (int j = 0; j < 64; j++) acc += wr[64+j]*hb[j];
        g_chvec[i] = acc;
    }
}

// ---------------- fv + assemble vec = [word_emb | chvec | fv] ----------------
__global__ void fv_vec_kernel(const float* __restrict__ features,
                              const float* __restrict__ featW, const float* __restrict__ featb,
                              const int* __restrict__ words2ix, const float* __restrict__ word_emb)
{
    for (int idx = blockIdx.x*blockDim.x + threadIdx.x; idx < NW*320; idx += gridDim.x*blockDim.x) {
        int w = idx / 320;
        int j = idx - w*320;
        float v;
        if (j < 128) {
            v = word_emb[ words2ix[w]*128 + j ];
        } else if (j < 192) {
            v = g_chvec[w*64 + (j-128)];
        } else {
            int m = j - 192;
            int b = w >> 7, s = w & 127;
            v = featb[m];
            #pragma unroll
            for (int f = 0; f < 4; f++) v += featW[m*4+f]*features[(b*4+f)*SS + s];
            g_fv[w*128 + m] = v;
        }
        g_vec[idx] = v;
    }
}

// ---------------- input GEMM: gx[(dir,t,b),1024] = vec @ Wih^T + (bih+bhh) ----------------
__global__ __launch_bounds__(256,2) void gx_gemm_kernel(
    const float* __restrict__ Wf, const float* __restrict__ Wb,
    const float* __restrict__ bihf, const float* __restrict__ bhhf,
    const float* __restrict__ bihb, const float* __restrict__ bhhb)
{
    int ntile = blockIdx.x, mtile = blockIdx.y;
    int dir = ntile >> 3;
    const float* W  = dir ? Wb : Wf;
    const float* bi = dir ? bihb : bihf;
    const float* bh = dir ? bhhb : bhhf;
    int n0 = (ntile & 7) * 128, m0 = mtile * 128;

    __shared__ float As[8][132];
    __shared__ float Bs[8][132];

    int tid = threadIdx.x;
    int lrow = tid >> 1, lk = (tid & 1) * 4;
    int m = m0 + lrow, tt = m >> 7, sq = m & 127;
    const float* arow = g_vec + (sq*SS + tt)*320;
    const float* brow = W + (n0 + lrow)*320;
    int tm = tid >> 4, tn = tid & 15;

    u64 acc[8][4];
    #pragma unroll
    for (int i=0;i<8;i++){ acc[i][0]=0ull; acc[i][1]=0ull; acc[i][2]=0ull; acc[i][3]=0ull; }

    for (int kb = 0; kb < 320; kb += 8) {
        float4 av = *(const float4*)(arow + kb + lk);
        float4 bv = *(const float4*)(brow + kb + lk);
        __syncthreads();
        As[lk+0][lrow]=av.x; As[lk+1][lrow]=av.y; As[lk+2][lrow]=av.z; As[lk+3][lrow]=av.w;
        Bs[lk+0][lrow]=bv.x; Bs[lk+1][lrow]=bv.y; Bs[lk+2][lrow]=bv.z; Bs[lk+3][lrow]=bv.w;
        __syncthreads();
        #pragma unroll
        for (int k=0;k<8;k++){
            float af[8];
            *(float4*)(af)   = *(const float4*)&As[k][tm*8];
            *(float4*)(af+4) = *(const float4*)&As[k][tm*8+4];
            ulonglong2 b0 = *(const ulonglong2*)&Bs[k][tn*8];
            ulonglong2 b1 = *(const ulonglong2*)&Bs[k][tn*8+4];
            #pragma unroll
            for (int i=0;i<8;i++){
                u64 ap = pack2(af[i], af[i]);
                acc[i][0]=ffma2(ap,b0.x,acc[i][0]);
                acc[i][1]=ffma2(ap,b0.y,acc[i][1]);
                acc[i][2]=ffma2(ap,b1.x,acc[i][2]);
                acc[i][3]=ffma2(ap,b1.y,acc[i][3]);
            }
        }
    }
    float biasv[8];
    #pragma unroll
    for (int j=0;j<8;j++){ int r = n0 + tn*8 + j; biasv[j] = bi[r] + bh[r]; }
    #pragma unroll
    for (int i=0;i<8;i++){
        int mm = m0 + tm*8 + i;
        int tq = mm >> 7, s = mm & 127;
        float* dst = g_gx + ((dir*SS + tq)*BB + s)*1024 + n0 + tn*8;
        float o[8];
        #pragma unroll
        for (int j2=0;j2<4;j2++){
            float2 f = unpack2(acc[i][j2]);
            o[2*j2]   = f.x + biasv[2*j2];
            o[2*j2+1] = f.y + biasv[2*j2+1];
        }
        *(float4*)(dst)   = *(float4*)(o);
        *(float4*)(dst+4) = *(float4*)(o+4);
    }
}

// ---------------- persistent recurrent BiLSTM ----------------
// 128 blocks = (dir, us 32-unit slice, sg 16-seq group). Whh slice in registers.
__global__ __launch_bounds__(256,1) void lstm_persist_kernel(
    const float* __restrict__ Whh_f, const float* __restrict__ Whh_b)
{
    const unsigned NB = 128;
    int bx = blockIdx.x, tid = threadIdx.x;
    int dir = bx >> 6, us = (bx >> 3) & 7, sg = bx & 7, sbase = sg*16;
    const float* Whh = dir ? Whh_b : Whh_f;
    int r = tid >> 1, kh = tid & 1, g = r >> 5, ul = r & 31, u = us*32 + ul;
    // update-role mapping
    int uul = tid & 31, usq = tid >> 5, uu = us*32 + uul;
    int sl0 = 2*usq;

    float w[128];
    #pragma unroll
    for (int k = 0; k < 128; k++) w[k] = Whh[(g*HHd + u)*HHd + kh*128 + k];

    __shared__ __align__(16) float xh[256*16];
    __shared__ __align__(16) float gsm[128*16];

    float cA = 0.f, cB = 0.f;

    #pragma unroll 1
    for (int ts = 0; ts < SS; ts++) {
        int tx = dir ? (SS-1-ts) : ts;
        // stage previous h (L2 only — L1 is stale across grid barrier)
        if (ts == 0) {
            float4 z = make_float4(0.f,0.f,0.f,0.f);
            float4* d = (float4*)&xh[tid*16];
            d[0]=z; d[1]=z; d[2]=z; d[3]=z;
        } else {
            const float4* sp = (const float4*)(g_hT + (((ts&1)*2 + dir)*8 + sg)*4096 + tid*16);
            float4* d = (float4*)&xh[tid*16];
            d[0]=__ldcg(sp+0); d[1]=__ldcg(sp+1); d[2]=__ldcg(sp+2); d[3]=__ldcg(sp+3);
        }
        __syncthreads();
        // prefetch gx for update phase
        float gxv[8];
        {
            int gb = ((dir*SS + tx)*BB + sbase + sl0)*1024 + uu;
            #pragma unroll
            for (int gq = 0; gq < 4; gq++) {
                gxv[gq*2+0] = __ldcg(&g_gx[gb + gq*256]);
                gxv[gq*2+1] = __ldcg(&g_gx[gb + 1024 + gq*256]);
            }
        }
        // recurrent matvec: row r, k-half kh, 16 seqs packed in pairs
        u64 acc[8];
        #pragma unroll
        for (int j=0;j<8;j++) acc[j]=0ull;
        const float* xb = xh + kh*128*16;
        #pragma unroll
        for (int k = 0; k < 128; k++) {
            const ulonglong2* xr = (const ulonglong2*)(xb + k*16);
            u64 wp = pack2(w[k], w[k]);
            ulonglong2 x0 = xr[0], x1 = xr[1];
            acc[0]=ffma2(wp,x0.x,acc[0]); acc[1]=ffma2(wp,x0.y,acc[1]);
            acc[2]=ffma2(wp,x1.x,acc[2]); acc[3]=ffma2(wp,x1.y,acc[3]);
            x0 = xr[2]; x1 = xr[3];
            acc[4]=ffma2(wp,x0.x,acc[4]); acc[5]=ffma2(wp,x0.y,acc[5]);
            acc[6]=ffma2(wp,x1.x,acc[6]); acc[7]=ffma2(wp,x1.y,acc[7]);
        }
        #pragma unroll
        for (int j=0;j<8;j++) {
            u64 o = __shfl_xor_sync(0xffffffffu, acc[j], 1);
            acc[j] = add2(acc[j], o);
        }
        if (kh == 0) {
            ulonglong2* gd = (ulonglong2*)&gsm[r*16];
            gd[0] = make_ulonglong2(acc[0],acc[1]);
            gd[1] = make_ulonglong2(acc[2],acc[3]);
            gd[2] = make_ulonglong2(acc[4],acc[5]);
            gd[3] = make_ulonglong2(acc[6],acc[7]);
        }
        __syncthreads();
        // pointwise LSTM update for (unit uu, seqs sl0, sl0+1)
        {
            float gi = gsm[(uul)*16      + sl0] + gxv[0];
            float gf = gsm[(32+uul)*16   + sl0] + gxv[2];
            float gg = gsm[(64+uul)*16   + sl0] + gxv[4];
            float go = gsm[(96+uul)*16   + sl0] + gxv[6];
            float iv=sigf(gi), fv=sigf(gf), gv=tanhfast(gg), ov=sigf(go);
            cA = fv*cA + iv*gv;
            float hA = ov*tanhfast(cA);

            gi = gsm[(uul)*16      + sl0+1] + gxv[1];
            gf = gsm[(32+uul)*16   + sl0+1] + gxv[3];
            gg = gsm[(64+uul)*16   + sl0+1] + gxv[5];
            go = gsm[(96+uul)*16   + sl0+1] + gxv[7];
            iv=sigf(gi); fv=sigf(gf); gv=tanhfast(gg); ov=sigf(go);
            cB = fv*cB + iv*gv;
            float hB = ov*tanhfast(cB);

            float* hdst = g_hT + ((((ts&1)^1)*2 + dir)*8 + sg)*4096 + uu*16 + sl0;
            hdst[0] = hA; hdst[1] = hB;
            int b0 = sbase + sl0;
            g_hout[(b0*SS + tx)*512 + dir*256 + uu]     = hA;
            g_hout[((b0+1)*SS + tx)*512 + dir*256 + uu] = hB;
        }
        // grid barrier (monotonic ticket; replay-safe)
        __syncthreads();
        if (tid == 0) {
            __threadfence();
            unsigned tk = atomicAdd(&g_bar_arrive, 1u) + 1u;
            unsigned target = ((tk + NB - 1u)/NB)*NB;
            if (tk == target) g_bar_release = target;
            else while (g_bar_release < target) __nanosleep(64);
            __threadfence();
        }
        __syncthreads();
    }
}

// ---------------- emissions + tag argmax ----------------
__global__ void feats_kernel(const float* __restrict__ tagW, const float* __restrict__ tagb,
                             float* __restrict__ out)
{
    int w = blockIdx.x;
    int lane = threadIdx.x;
    float xv[22];
    #pragma unroll
    for (int i = 0; i < 22; i++) {
        int j = lane + 32*i;
        float v;
        if (j < 512)      v = g_hout[w*512 + j];
        else if (j < 576) v = g_chvec[w*64 + (j-512)];
        else              v = g_fv[w*128 + (j-576)];
        xv[i] = v;
    }
    float best = -1e30f; int bestk = 0;
    for (int k = 0; k < KK; k++) {
        float acc = 0.f;
        const float* wr = tagW + k*704;
        #pragma unroll
        for (int i = 0; i < 22; i++) acc += wr[lane + 32*i]*xv[i];
        #pragma unroll
        for (int off = 16; off; off >>= 1) acc += __shfl_xor_sync(0xffffffffu, acc, off);
        acc += tagb[k];
        if (lane == 0) g_feats[w*KK + k] = acc;
        if (acc > best) { best = acc; bestk = k; }
    }
    if (lane == 0) out[BB + NW + w] = (float)bestk;
}

// ---------------- CRF Viterbi ----------------
__global__ void viterbi_kernel(const int* __restrict__ mask, const float* __restrict__ trans,
                               float* __restrict__ out)
{
    int b = blockIdx.x;
    int k = threadIdx.x;
    __shared__ float sc[KK];
    __shared__ float tr[KK*KK];
    __shared__ float fins[32];
    for (int i = k; i < KK*KK; i += 32) tr[i] = trans[i];
    if (k < KK) sc[k] = g_feats[(b*SS + 0)*KK + k] + trans[NSTART*KK + k];
    __syncwarp();
    for (int step = 1; step < SS; step++) {
        float best = -1e30f; int bp = 0;
        if (k < KK) {
            #pragma unroll
            for (int p = 0; p < KK; p++) {
                float v = sc[p] + tr[p*KK + k];
                if (v > best) { best = v; bp = p; }
            }
            best += g_feats[(b*SS + step)*KK + k];
            if (mask[b*SS + step] == 0) { best = sc[k]; bp = k; }
        }
        __syncwarp();
        if (k < KK) { sc[k] = best; g_bp[((step-1)*BB + b)*KK + k] = bp; }
        __syncwarp();
    }
    float fin = (k < KK) ? (sc[k] + tr[k*KK + NSTOP]) : -1e30f;
    fins[k] = fin;
    __syncwarp();
    if (k == 0) {
        float best = -1e30f; int bt = 0;
        for (int p = 0; p < KK; p++) if (fins[p] > best) { best = fins[p]; bt = p; }
        out[b] = best;
        int tag = bt;
        out[BB + b*SS + (SS-1)] = (float)tag;
        for (int step = SS-1; step >= 1; step--) {
            tag = g_bp[((step-1)*BB + b)*KK + tag];
            out[BB + b*SS + (step-1)] = (float)tag;
        }
    }
}

// ---------------- launch ----------------
extern "C" void kernel_launch(void* const* d_in, const int* in_sizes, int n_in,
                              void* d_out, int out_size)
{
    (void)in_sizes; (void)n_in; (void)out_size;
    const int*   words2ix  = (const int*)  d_in[0];
    const int*   chars2ix  = (const int*)  d_in[1];
    const float* features  = (const float*)d_in[2];
    const int*   mask      = (const int*)  d_in[3];
    const float* word_emb  = (const float*)d_in[4];
    const float* char_emb  = (const float*)d_in[5];
    const float* cWih_f = (const float*)d_in[6];
    const float* cWhh_f = (const float*)d_in[7];
    const float* cbih_f = (const float*)d_in[8];
    const float* cbhh_f = (const float*)d_in[9];
    const float* cWih_b = (const float*)d_in[10];
    const float* cWhh_b = (const float*)d_in[11];
    const float* cbih_b = (const float*)d_in[12];
    const float* cbhh_b = (const float*)d_in[13];
    const float* coW    = (const float*)d_in[14];
    const float* cob    = (const float*)d_in[15];
    const float* featW  = (const float*)d_in[16];
    const float* featb  = (const float*)d_in[17];
    const float* lWih_f = (const float*)d_in[18];
    const float* lWhh_f = (const float*)d_in[19];
    const float* lbih_f = (const float*)d_in[20];
    const float* lbhh_f = (const float*)d_in[21];
    const float* lWih_b = (const float*)d_in[22];
    const float* lWhh_b = (const float*)d_in[23];
    const float* lbih_b = (const float*)d_in[24];
    const float* lbhh_b = (const float*)d_in[25];
    const float* tagW   = (const float*)d_in[26];
    const float* tagb   = (const float*)d_in[27];
    const float* trans  = (const float*)d_in[28];
    float* out = (float*)d_out;

    char_lstm_kernel<<<dim3(512,2), 256>>>(chars2ix, char_emb,
        cWih_f, cWhh_f, cbih_f, cbhh_f, cWih_b, cWhh_b, cbih_b, cbhh_b);
    chvec_kernel<<<512, 256>>>(coW, cob);
    fv_vec_kernel<<<512, 256>>>(features, featW, featb, words2ix, word_emb);
    gx_gemm_kernel<<<dim3(16,128), 256>>>(lWih_f, lWih_b, lbih_f, lbhh_f, lbih_b, lbhh_b);
    lstm_persist_kernel<<<128, 256>>>(lWhh_f, lWhh_b);
    feats_kernel<<<NW, 32>>>(tagW, tagb, out);
    viterbi_kernel<<<BB, 32>>>(mask, trans, out);
}